// round 1
// baseline (speedup 1.0000x reference)
#include <cuda_runtime.h>

// ---------------- problem constants (fixed by dataset) ----------------
#define KB    2        // batch
#define KNV   6        // views
#define KM    1369     // tokens (37*37)
#define KDIM  384      // token dim
#define KV    65536    // voxels per batch
#define KPF   64       // per-voxel feature dim
#define KHID  256      // hidden
#define KOUT  16       // output
#define KGRID 37
#define KGV   (KB*KV)  // 131072 total voxels

// ---------------- device scratch (no allocations allowed) -------------
__device__ float g_mean[KB*KM*KDIM];   // [2738][384]  mean over views
__device__ float g_T[KB*KM*KHID];      // [2738][256]  mean_tokens @ W1[64:] + b1

// =======================================================================
// Kernel A: mean over views.  patch_tokens [B, NV, M, DIM] -> g_mean
// =======================================================================
__global__ void mean_kernel(const float* __restrict__ pt) {
    int i = blockIdx.x * blockDim.x + threadIdx.x;     // float4 index
    const int total4 = KB * KM * KDIM / 4;
    if (i >= total4) return;
    const int dq = i % (KDIM / 4);
    const int bm = i / (KDIM / 4);
    const int b = bm / KM;
    const int m = bm % KM;
    const float4* base = (const float4*)pt;
    float4 s = make_float4(0.f, 0.f, 0.f, 0.f);
#pragma unroll
    for (int vw = 0; vw < KNV; vw++) {
        float4 x = base[((size_t)(b * KNV + vw) * KM + m) * (KDIM / 4) + dq];
        s.x += x.x; s.y += x.y; s.z += x.z; s.w += x.w;
    }
    const float inv = 1.0f / KNV;
    s.x *= inv; s.y *= inv; s.z *= inv; s.w *= inv;
    ((float4*)g_mean)[i] = s;
}

// =======================================================================
// Kernel B: table GEMM  g_T[r, j] = sum_k g_mean[r,k] * W1[64+k, j] + b1[j]
// r in [0,2738), j in [0,256), k in [0,384).
// Tile: 32 rows x 64 cols per block, 256 threads, micro 2x4, K-tile 16.
// =======================================================================
#define TBM 32
#define TBN 64
#define TBK 16
__global__ void table_kernel(const float* __restrict__ W1,
                             const float* __restrict__ b1) {
    __shared__ float As[TBK][TBM + 1];
    __shared__ float Bs[TBK][TBN];
    const int ROWS = KB * KM;                 // 2738
    const int t  = threadIdx.x;
    const int m0 = blockIdx.x * TBM;
    const int j0 = blockIdx.y * TBN;
    const int ty = t >> 4;                    // 0..15 -> 2 rows each
    const int tx = t & 15;                    // 0..15 -> 4 cols each

    float acc[2][4] = {};

    for (int k0 = 0; k0 < KDIM; k0 += TBK) {
        // load A tile: 32 rows x 16 k  (float2 per thread, coalesced along k)
        {
            int idx = t * 2;
            int m  = idx / TBK;
            int kk = idx % TBK;               // even
            float2 v = make_float2(0.f, 0.f);
            if (m0 + m < ROWS)
                v = *(const float2*)&g_mean[(size_t)(m0 + m) * KDIM + k0 + kk];
            As[kk][m]     = v.x;
            As[kk + 1][m] = v.y;
        }
        // load B tile: 16 k x 64 j (float4 per thread, coalesced along j)
        {
            int kk = t >> 4;
            int jq = (t & 15) * 4;
            *(float4*)&Bs[kk][jq] =
                *(const float4*)&W1[(size_t)(KPF + k0 + kk) * KHID + j0 + jq];
        }
        __syncthreads();
#pragma unroll
        for (int kk = 0; kk < TBK; kk++) {
            float a0 = As[kk][ty * 2 + 0];
            float a1 = As[kk][ty * 2 + 1];
            float4 b4 = *(const float4*)&Bs[kk][tx * 4];
            acc[0][0] += a0 * b4.x; acc[0][1] += a0 * b4.y;
            acc[0][2] += a0 * b4.z; acc[0][3] += a0 * b4.w;
            acc[1][0] += a1 * b4.x; acc[1][1] += a1 * b4.y;
            acc[1][2] += a1 * b4.z; acc[1][3] += a1 * b4.w;
        }
        __syncthreads();
    }

    float4 bb = *(const float4*)&b1[j0 + tx * 4];
#pragma unroll
    for (int i = 0; i < 2; i++) {
        int r = m0 + ty * 2 + i;
        if (r < ROWS) {
            float4 o;
            o.x = acc[i][0] + bb.x; o.y = acc[i][1] + bb.y;
            o.z = acc[i][2] + bb.z; o.w = acc[i][3] + bb.w;
            *(float4*)&g_T[(size_t)r * KHID + j0 + tx * 4] = o;
        }
    }
}

// =======================================================================
// Kernel C: fused main kernel. Per block: 64 voxels.
//   1) project coords -> token index (per voxel)
//   2) GEMM1: [64 voxels x 64 feats] @ W1[0:64, 0:256]  (8x8 register tiles)
//   3) epilogue: + gathered g_T row, relu -> Hs (shared, reuses W1 region)
//   4) GEMM2: Hs[64x256] @ W2[256x16] + b2 -> out
// Shared layout (floats):
//   [0, 16640)      W1s [64][256]   (union with Hs [64][260])
//   [16640, 20992)  As  [64][68]    As[k][v]  (transposed voxel feats)
//   [20992, 25088)  W2s [256][16]
//   [25088, 25152)  sIdx[64] (int, = b*KM + flat_idx)
// =======================================================================
#define VB 64
#define HS_STRIDE 260
#define AS_STRIDE 68
#define AS_OFF    16640
#define W2_OFF    20992
#define IDX_OFF   25088
#define SMEMC_FLOATS 25152
#define SMEMC_BYTES  (SMEMC_FLOATS * 4)

__global__ void __launch_bounds__(256, 2)
fused_kernel(const float* __restrict__ vf, const float* __restrict__ vc,
             const float* __restrict__ Km, const float* __restrict__ Rt,
             const float* __restrict__ W1, const float* __restrict__ W2,
             const float* __restrict__ b2, float* __restrict__ out) {
    extern __shared__ float sm[];
    float* W1s = sm;                       // [64][256]
    float* Hs  = sm;                       // [64][260] (after GEMM1 sync)
    float* As  = sm + AS_OFF;              // [64][68]
    float* W2s = sm + W2_OFF;              // [256][16]
    int*   sIdx = (int*)(sm + IDX_OFF);    // [64]

    const int t  = threadIdx.x;
    const int g0 = blockIdx.x * VB;        // first global voxel of this block

    // ---- stage W1 top-64 rows: first 4096 float4 of W1 ----
    {
        const float4* src = (const float4*)W1;
        float4* dst = (float4*)W1s;
#pragma unroll
        for (int r = 0; r < 16; r++) dst[t + r * 256] = src[t + r * 256];
    }
    // ---- stage W2 [256][16] = 1024 float4 ----
    {
        const float4* src = (const float4*)W2;
        float4* dst = (float4*)W2s;
#pragma unroll
        for (int r = 0; r < 4; r++) dst[t + r * 256] = src[t + r * 256];
    }
    // ---- stage voxel features transposed: As[k][v] ----
    {
#pragma unroll
        for (int r = 0; r < 16; r++) {
            int i = t + r * 256;           // 0..4095
            int v = i >> 6;
            int k = i & 63;
            As[k * AS_STRIDE + v] = vf[((size_t)(g0 + v)) * KPF + k];
        }
    }
    // ---- projection -> token index (includes batch offset) ----
    if (t < VB) {
        int g = g0 + t;
        int b = g >> 16;                   // KV = 65536
        const float* c = vc + (size_t)g * 3;
        float x = c[0], y = c[1], z = c[2];
        float cam0 = Rt[0] * x + Rt[1] * y + Rt[2]  * z + Rt[3];
        float cam1 = Rt[4] * x + Rt[5] * y + Rt[6]  * z + Rt[7];
        float cam2 = Rt[8] * x + Rt[9] * y + Rt[10] * z + Rt[11];
        float p0 = Km[0] * cam0 + Km[1] * cam1 + Km[2] * cam2;
        float p1 = Km[3] * cam0 + Km[4] * cam1 + Km[5] * cam2;
        float p2 = Km[6] * cam0 + Km[7] * cam1 + Km[8] * cam2;
        float denom = p2 + 1e-6f;
        float u  = __fdiv_rn(p0, denom) * (float)(518.0 / 600.0);
        float vv = __fdiv_rn(p1, denom) * (float)(518.0 / 900.0);
        int px = (int)__fdiv_rn(u, 14.0f);      // truncate toward zero
        int py = (int)__fdiv_rn(vv, 14.0f);
        px = min(max(px, 0), KGRID - 1);
        py = min(max(py, 0), KGRID - 1);
        sIdx[t] = b * KM + px * KGRID + py;
    }
    __syncthreads();

    // ---- GEMM1: acc[i][j] = sum_k As[k][vr+i] * W1s[k][jc+j] ----
    const int tx = t & 31;                 // 32 col groups of 8
    const int ty = t >> 5;                 // 8 voxel groups of 8
    const int jc = tx * 8;
    const int vr = ty * 8;
    float acc[8][8] = {};
#pragma unroll 4
    for (int k = 0; k < 64; k++) {
        float4 a0  = *(const float4*)(As + k * AS_STRIDE + vr);
        float4 a1  = *(const float4*)(As + k * AS_STRIDE + vr + 4);
        float4 b0  = *(const float4*)(W1s + k * 256 + jc);
        float4 b1v = *(const float4*)(W1s + k * 256 + jc + 4);
        float a[8] = {a0.x, a0.y, a0.z, a0.w, a1.x, a1.y, a1.z, a1.w};
        float bb[8] = {b0.x, b0.y, b0.z, b0.w, b1v.x, b1v.y, b1v.z, b1v.w};
#pragma unroll
        for (int i = 0; i < 8; i++)
#pragma unroll
            for (int j = 0; j < 8; j++)
                acc[i][j] += a[i] * bb[j];
    }
    __syncthreads();   // everyone done reading W1s before it becomes Hs

    // ---- epilogue: + gathered T row, relu, stage into Hs ----
#pragma unroll
    for (int i = 0; i < 8; i++) {
        int row = sIdx[vr + i];
        const float* trow = g_T + (size_t)row * KHID + jc;
        float4 t0 = *(const float4*)trow;
        float4 t1 = *(const float4*)(trow + 4);
        float4 h0, h1;
        h0.x = fmaxf(acc[i][0] + t0.x, 0.f);
        h0.y = fmaxf(acc[i][1] + t0.y, 0.f);
        h0.z = fmaxf(acc[i][2] + t0.z, 0.f);
        h0.w = fmaxf(acc[i][3] + t0.w, 0.f);
        h1.x = fmaxf(acc[i][4] + t1.x, 0.f);
        h1.y = fmaxf(acc[i][5] + t1.y, 0.f);
        h1.z = fmaxf(acc[i][6] + t1.z, 0.f);
        h1.w = fmaxf(acc[i][7] + t1.w, 0.f);
        *(float4*)(Hs + (vr + i) * HS_STRIDE + jc)     = h0;
        *(float4*)(Hs + (vr + i) * HS_STRIDE + jc + 4) = h1;
    }
    __syncthreads();

    // ---- GEMM2: out[v2, og..og+3] = Hs[v2,:] @ W2[:, og..og+3] + b2 ----
    const int v2 = t >> 2;                 // 0..63
    const int og = (t & 3) * 4;            // 0,4,8,12
    float4 bv = *(const float4*)(b2 + og);
    float o0 = bv.x, o1 = bv.y, o2 = bv.z, o3 = bv.w;
    const float4* hrow = (const float4*)(Hs + v2 * HS_STRIDE);
#pragma unroll 4
    for (int k4 = 0; k4 < 64; k4++) {
        float4 h4 = hrow[k4];
        float4 w0 = *(const float4*)(W2s + (k4 * 4 + 0) * KOUT + og);
        float4 w1 = *(const float4*)(W2s + (k4 * 4 + 1) * KOUT + og);
        float4 w2 = *(const float4*)(W2s + (k4 * 4 + 2) * KOUT + og);
        float4 w3 = *(const float4*)(W2s + (k4 * 4 + 3) * KOUT + og);
        o0 += h4.x * w0.x + h4.y * w1.x + h4.z * w2.x + h4.w * w3.x;
        o1 += h4.x * w0.y + h4.y * w1.y + h4.z * w2.y + h4.w * w3.y;
        o2 += h4.x * w0.z + h4.y * w1.z + h4.z * w2.z + h4.w * w3.z;
        o3 += h4.x * w0.w + h4.y * w1.w + h4.z * w2.w + h4.w * w3.w;
    }
    float4 o = make_float4(o0, o1, o2, o3);
    *(float4*)(out + ((size_t)(g0 + v2)) * KOUT + og) = o;
}

// =======================================================================
extern "C" void kernel_launch(void* const* d_in, const int* in_sizes, int n_in,
                              void* d_out, int out_size) {
    (void)in_sizes; (void)n_in; (void)out_size;
    const float* pt = (const float*)d_in[0];
    const float* vf = (const float*)d_in[1];
    const float* vc = (const float*)d_in[2];
    const float* Km = (const float*)d_in[3];
    const float* Rt = (const float*)d_in[4];
    const float* W1 = (const float*)d_in[5];
    const float* b1 = (const float*)d_in[6];
    const float* W2 = (const float*)d_in[7];
    const float* b2 = (const float*)d_in[8];
    float* out = (float*)d_out;

    const int total4 = KB * KM * KDIM / 4;
    mean_kernel<<<(total4 + 255) / 256, 256>>>(pt);

    dim3 gridB((KB * KM + TBM - 1) / TBM, KHID / TBN);   // (86, 4)
    table_kernel<<<gridB, 256>>>(W1, b1);

    cudaFuncSetAttribute(fused_kernel,
                         cudaFuncAttributeMaxDynamicSharedMemorySize,
                         SMEMC_BYTES);
    fused_kernel<<<KGV / VB, 256, SMEMC_BYTES>>>(vf, vc, Km, Rt, W1, W2, b2, out);
}